// round 7
// baseline (speedup 1.0000x reference)
#include <cuda_runtime.h>
#include <math.h>

#define H 128
#define LAYERS 4
#define NMAX 50176
#define EMAX 700000
#define EPS 1e-8f
#define FR 136   // fragment-pack stride in floats (128 + 8 pad)
#define MS 132   // phase-3 message smem row stride (floats)

// ---------------- static device scratch (allocation-free rule) ----------------
__device__ float g_h[NMAX * H];
__device__ float g_A[NMAX * H];     // (h @ msgW1[0:128])   -> indexed by dst
__device__ float g_B[NMAX * H];     // (h @ msgW1[128:256]) -> indexed by src
__device__ float g_agg[NMAX * H];   // message scatter target
__device__ float g_T[NMAX * H];     // generic temp
__device__ float g_pos[NMAX * 3];
__device__ float g_dpos[NMAX * 3];
__device__ float g_wnode[NMAX];
__device__ int   g_cnt[NMAX];       // per-dst degree
__device__ int   g_bsum[256];       // block partial sums for scan
__device__ int   g_cursor[NMAX];    // scatter cursors (start offsets)
__device__ int   g_esrc[EMAX];      // dst-sorted edge sources
__device__ int   g_edst[EMAX];      // dst-sorted edge dests

__device__ __forceinline__ float silu_f(float x) {
    return x / (1.0f + __expf(-x));
}

__device__ __forceinline__ unsigned f2tf(float x) {
    unsigned r;
    asm("cvt.rna.tf32.f32 %0, %1;" : "=r"(r) : "f"(x));
    return r;
}

__device__ __forceinline__ void mma_tf32(float c[4], const unsigned a[4], const unsigned b[2]) {
    asm volatile(
        "mma.sync.aligned.m16n8k8.row.col.f32.tf32.tf32.f32 "
        "{%0,%1,%2,%3}, {%4,%5,%6,%7}, {%8,%9}, {%0,%1,%2,%3};"
        : "+f"(c[0]), "+f"(c[1]), "+f"(c[2]), "+f"(c[3])
        : "r"(a[0]), "r"(a[1]), "r"(a[2]), "r"(a[3]), "r"(b[0]), "r"(b[1]));
}

__device__ __forceinline__ void red_add_v4(float* addr, float a, float b, float c, float d) {
    asm volatile("red.global.add.v4.f32 [%0], {%1,%2,%3,%4};"
                 :: "l"(addr), "f"(a), "f"(b), "f"(c), "f"(d) : "memory");
}

// fragment-packed smem address for (row r in 0..63, k in 0..127)
__device__ __forceinline__ int fp_addr(int r, int k) {
    return ((r >> 4) * 16 + (k >> 3)) * FR + ((r & 7) * 4 + (k & 3)) * 4
         + ((r >> 3) & 1) + 2 * ((k >> 2) & 1);
}

// ================= counting sort of edges by dst ==============================
__global__ void hist_kernel(const int* __restrict__ ei, int E, int Etot,
                            int* __restrict__ cnt) {
    int e = blockIdx.x * blockDim.x + threadIdx.x;
    if (e >= Etot) return;
    int d = (e < E) ? ei[E + e] : (e - E);
    atomicAdd(cnt + d, 1);
}

__global__ void psum_kernel(const int* __restrict__ cnt, int n, int* __restrict__ bsum) {
    __shared__ int sm[256];
    int i = blockIdx.x * 256 + threadIdx.x;
    sm[threadIdx.x] = (i < n) ? cnt[i] : 0;
    __syncthreads();
    for (int o = 128; o > 0; o >>= 1) {
        if (threadIdx.x < o) sm[threadIdx.x] += sm[threadIdx.x + o];
        __syncthreads();
    }
    if (threadIdx.x == 0) bsum[blockIdx.x] = sm[0];
}

__global__ void scanb_kernel(int* __restrict__ bsum, int nb) {
    if (threadIdx.x == 0 && blockIdx.x == 0) {
        int run = 0;
        for (int b = 0; b < nb; ++b) { int t = bsum[b]; bsum[b] = run; run += t; }
    }
}

__global__ void offs_kernel(const int* __restrict__ cnt, int n,
                            const int* __restrict__ bsum, int* __restrict__ cursor) {
    int tid = threadIdx.x, lane = tid & 31, w = tid >> 5;
    int i = blockIdx.x * 256 + tid;
    int v = (i < n) ? cnt[i] : 0;
    int x = v;
    for (int o = 1; o < 32; o <<= 1) {
        int y = __shfl_up_sync(0xffffffffu, x, o);
        if (lane >= o) x += y;
    }
    __shared__ int ws[8];
    if (lane == 31) ws[w] = x;
    __syncthreads();
    if (w == 0 && lane < 8) {
        int z = ws[lane];
        for (int o = 1; o < 8; o <<= 1) {
            int y = __shfl_up_sync(0xffu, z, o);
            if (lane >= o) z += y;
        }
        ws[lane] = z;
    }
    __syncthreads();
    int incl = x + (w ? ws[w - 1] : 0);
    if (i < n) cursor[i] = bsum[blockIdx.x] + incl - v;
}

__global__ void scatter_kernel(const int* __restrict__ ei, int E, int Etot,
                               int* __restrict__ cursor,
                               int* __restrict__ esrc, int* __restrict__ edst) {
    int e = blockIdx.x * blockDim.x + threadIdx.x;
    if (e >= Etot) return;
    int s, d;
    if (e < E) { s = ei[e]; d = ei[E + e]; }
    else       { s = e - E; d = s; }
    int p = atomicAdd(cursor + d, 1);
    esrc[p] = s; edst[p] = d;
}

// ---------------- node-side GEMM (tf32 mma), 64-row tiles, 256 threads --------
template <int KS>
__device__ __forceinline__ void node_chunk64(
    const float* __restrict__ src, int stride, int coff, int kc,
    const float* __restrict__ W,
    float (&d)[4][2][4], float* Xs, int n, int row0)
{
    const int tid = threadIdx.x;
    const int lane = tid & 31;
    const int wn = tid >> 5;
    const int g = lane >> 2, t = lane & 3;

    __syncthreads();
    constexpr int Q4 = KS * 2;
#pragma unroll
    for (int q = tid; q < 64 * Q4; q += 256) {
        int r = q / Q4;
        int kq = (q - r * Q4) << 2;
        int row = row0 + r;
        float4 v = make_float4(0.f, 0.f, 0.f, 0.f);
        if (row < n) v = *(const float4*)(src + (size_t)row * stride + coff + kq);
        float vv[4] = {v.x, v.y, v.z, v.w};
#pragma unroll
        for (int s2 = 0; s2 < 4; ++s2)
            Xs[fp_addr(r, kq + s2)] = __uint_as_float(f2tf(vv[s2]));
    }
    __syncthreads();

    const int ncol0 = wn * 16 + g;
#pragma unroll
    for (int kk = 0; kk < KS; ++kk) {
        const float* wr = W + (size_t)(kc + kk * 8 + t) * H;
        unsigned bb0[2], bb1[2];
        bb0[0] = f2tf(__ldg(wr + ncol0));
        bb0[1] = f2tf(__ldg(wr + 4 * H + ncol0));
        bb1[0] = f2tf(__ldg(wr + ncol0 + 8));
        bb1[1] = f2tf(__ldg(wr + 4 * H + ncol0 + 8));
#pragma unroll
        for (int mt = 0; mt < 4; ++mt) {
            float4 av = *(const float4*)(Xs + (mt * 16 + kk) * FR + lane * 4);
            unsigned a[4] = {__float_as_uint(av.x), __float_as_uint(av.y),
                             __float_as_uint(av.z), __float_as_uint(av.w)};
            mma_tf32(d[mt][0], a, bb0);
            mma_tf32(d[mt][1], a, bb1);
        }
    }
}

// act: 0 = none, 1 = silu, 2 = silu + wnode-dot (no Y store)
__device__ __forceinline__ void gemm_body64(
    const float* __restrict__ X1, int K1,
    const float* __restrict__ X2, int K2,
    const float* __restrict__ W,
    const float* __restrict__ bias,
    const float* __restrict__ res,
    int act,
    float* __restrict__ Y, int n, int row0, float* Xs,
    const float* __restrict__ w2vec, float* __restrict__ wnout)
{
    const int tid = threadIdx.x;
    const int lane = tid & 31;
    const int wn = tid >> 5;
    const int g = lane >> 2, t = lane & 3;

    float d[4][2][4];
#pragma unroll
    for (int mt = 0; mt < 4; ++mt)
#pragma unroll
        for (int j = 0; j < 2; ++j)
#pragma unroll
            for (int s = 0; s < 4; ++s) d[mt][j][s] = 0.0f;

    const int Ktot = K1 + K2;
    for (int kc = 0; kc < Ktot; kc += 128) {
        const int kchunk = min(128, Ktot - kc);
        const float* src; int stride, coff;
        if (kc < K1) { src = X1; stride = K1; coff = kc; }
        else         { src = X2; stride = K2; coff = kc - K1; }
        if (kchunk == 128) node_chunk64<16>(src, stride, coff, kc, W, d, Xs, n, row0);
        else               node_chunk64<8>(src, stride, coff, kc, W, d, Xs, n, row0);
    }

    if (act == 2) {
        float b0[2], b1v[2], w20[2], w21[2];
#pragma unroll
        for (int j = 0; j < 2; ++j) {
            const int col = wn * 16 + j * 8 + t * 2;
            b0[j] = bias ? bias[col] : 0.0f;
            b1v[j] = bias ? bias[col + 1] : 0.0f;
            w20[j] = w2vec[col];
            w21[j] = w2vec[col + 1];
        }
#pragma unroll
        for (int mt = 0; mt < 4; ++mt) {
#pragma unroll
            for (int half = 0; half < 2; ++half) {
                int row = row0 + mt * 16 + g + half * 8;
                float s = 0.0f;
#pragma unroll
                for (int j = 0; j < 2; ++j) {
                    float o0 = silu_f(d[mt][j][half * 2 + 0] + b0[j]);
                    float o1 = silu_f(d[mt][j][half * 2 + 1] + b1v[j]);
                    s = fmaf(o0, w20[j], fmaf(o1, w21[j], s));
                }
                s += __shfl_xor_sync(0xffffffffu, s, 1);
                s += __shfl_xor_sync(0xffffffffu, s, 2);
                if (t == 0 && row < n) atomicAdd(wnout + row, s);
            }
        }
        return;
    }

#pragma unroll
    for (int j = 0; j < 2; ++j) {
        const int col = wn * 16 + j * 8 + t * 2;
        float b0 = bias ? bias[col] : 0.0f;
        float b1v = bias ? bias[col + 1] : 0.0f;
#pragma unroll
        for (int mt = 0; mt < 4; ++mt) {
#pragma unroll
            for (int half = 0; half < 2; ++half) {
                int row = row0 + mt * 16 + g + half * 8;
                if (row < n) {
                    float o0 = d[mt][j][half * 2 + 0] + b0;
                    float o1 = d[mt][j][half * 2 + 1] + b1v;
                    if (act == 1) { o0 = silu_f(o0); o1 = silu_f(o1); }
                    if (res) {
                        o0 += res[(size_t)row * H + col];
                        o1 += res[(size_t)row * H + col + 1];
                    }
                    *(float2*)(Y + (size_t)row * H + col) = make_float2(o0, o1);
                }
            }
        }
    }
}

__global__ __launch_bounds__(256, 3) void node_gemm(
    const float* __restrict__ X1, int K1,
    const float* __restrict__ X2, int K2,
    const float* __restrict__ W,
    const float* __restrict__ bias,
    const float* __restrict__ res,
    int act,
    float* __restrict__ Y, int n)
{
    extern __shared__ float Xs[];
    gemm_body64(X1, K1, X2, K2, W, bias, res, act, Y, n, blockIdx.x * 64, Xs,
                nullptr, nullptr);
}

__global__ __launch_bounds__(256, 3) void fused3_gemm(
    const float* __restrict__ hbuf,
    const float* __restrict__ cW1, const float* __restrict__ cB1,
    const float* __restrict__ cW2, float* __restrict__ wn,
    const float* __restrict__ W1a, const float* __restrict__ W1b,
    float* __restrict__ A, float* __restrict__ B, int n)
{
    extern __shared__ float Xs[];
    if (blockIdx.y == 0) {
        gemm_body64(hbuf, H, nullptr, 0, cW1, cB1, nullptr, 2, nullptr, n,
                    blockIdx.x * 64, Xs, cW2, wn);
    } else if (blockIdx.y == 1) {
        gemm_body64(hbuf, H, nullptr, 0, W1a, nullptr, nullptr, 0, A, n,
                    blockIdx.x * 64, Xs, nullptr, nullptr);
    } else {
        gemm_body64(hbuf, H, nullptr, 0, W1b, nullptr, nullptr, 0, B, n,
                    blockIdx.x * 64, Xs, nullptr, nullptr);
    }
}

// ---------------- fused edge kernel (dst-sorted, segmented scatter) -----------
#define TE 64
__global__ __launch_bounds__(256, 3) void edge_kernel(
    const int* __restrict__ esrc, const int* __restrict__ edst, int Etot,
    const float* __restrict__ A, const float* __restrict__ B,
    const float* __restrict__ pos, const float* __restrict__ wnode,
    const float* __restrict__ W2, const float* __restrict__ b1,
    const float* __restrict__ b2, const float* __restrict__ w1c,
    float* __restrict__ agg, float* __restrict__ dpos)
{
    extern __shared__ float smbuf[];
    float* U = smbuf;                      // 64*FR floats; reused as Ms (64*MS)
    float* sdist = smbuf + 64 * FR;        // 64
    float* sinv  = sdist + TE;             // 64
    float* srx   = sinv + TE;              // 64
    float* sry   = srx + TE;               // 64
    float* srz   = sry + TE;               // 64
    int* ssrc = (int*)(srz + TE);          // 64
    int* sdst = ssrc + TE;                 // 64

    const int tid = threadIdx.x;
    const int lane = tid & 31;
    const int wn = tid >> 5;
    const int g = lane >> 2, t = lane & 3;

    const int fq = lane;
    const int eg = wn;
    const float4 w1c4 = *(const float4*)(w1c + fq * 4);
    const float4 b1_4 = *(const float4*)(b1 + fq * 4);
    const int fragk = fq >> 1;
    const int slot2 = 2 * (fq & 1);
    float b2v[2][2];
#pragma unroll
    for (int j = 0; j < 2; ++j) {
        b2v[j][0] = b2[wn * 16 + j * 8 + t * 2];
        b2v[j][1] = b2[wn * 16 + j * 8 + t * 2 + 1];
    }
    const int ncol0 = wn * 16 + g;

    const int ntiles = (Etot + TE - 1) / TE;
    for (int tile = blockIdx.x; tile < ntiles; tile += gridDim.x) {
        const int e0 = tile * TE;
        const int cnt = min(TE, Etot - e0);

        // ---- meta ----
        if (tid < TE) {
            int e = e0 + tid;
            int s = 0, dd = 0; float dist = 0.f, inv = 0.f;
            float rx = 0.f, ry = 0.f, rz = 0.f;
            if (tid < cnt) {
                s = esrc[e]; dd = edst[e];
                rx = pos[s * 3 + 0] - pos[dd * 3 + 0];
                ry = pos[s * 3 + 1] - pos[dd * 3 + 1];
                rz = pos[s * 3 + 2] - pos[dd * 3 + 2];
                dist = sqrtf(rx * rx + ry * ry + rz * rz);
                inv = wnode[s] / (dist + EPS);
            }
            ssrc[tid] = s; sdst[tid] = dd; sdist[tid] = dist; sinv[tid] = inv;
            srx[tid] = rx; sry[tid] = ry; srz[tid] = rz;
        }
        __syncthreads();

        // ---- phase 1: u frag-packed (LDG.128 gathers; dst rows L1-repeat) ----
#pragma unroll
        for (int i = 0; i < 8; ++i) {
            int e = eg * 8 + i;
            int s = ssrc[e], dd = sdst[e];
            float dist = sdist[e];
            float4 a4 = *(const float4*)(A + (size_t)dd * H + fq * 4);
            float4 c4 = *(const float4*)(B + (size_t)s * H + fq * 4);
            int base0 = ((e >> 4) * 16 + fragk) * FR + (e & 7) * 16
                      + ((e >> 3) & 1) + slot2;
            U[base0 + 0]  = __uint_as_float(f2tf(silu_f(a4.x + c4.x + dist * w1c4.x + b1_4.x)));
            U[base0 + 4]  = __uint_as_float(f2tf(silu_f(a4.y + c4.y + dist * w1c4.y + b1_4.y)));
            U[base0 + 8]  = __uint_as_float(f2tf(silu_f(a4.z + c4.z + dist * w1c4.z + b1_4.z)));
            U[base0 + 12] = __uint_as_float(f2tf(silu_f(a4.w + c4.w + dist * w1c4.w + b1_4.w)));
        }

        // ---- coord update: run-head threads sum their dst-run ----
        if (tid < cnt && (tid == 0 || sdst[tid] != sdst[tid - 1])) {
            int dd = sdst[tid];
            float sx = 0.f, sy = 0.f, sz = 0.f;
            int j = tid;
            do {
                float iv = sinv[j];
                sx = fmaf(srx[j], iv, sx);
                sy = fmaf(sry[j], iv, sy);
                sz = fmaf(srz[j], iv, sz);
                ++j;
            } while (j < cnt && sdst[j] == dd);
            atomicAdd(dpos + dd * 3 + 0, sx);
            atomicAdd(dpos + dd * 3 + 1, sy);
            atomicAdd(dpos + dd * 3 + 2, sz);
        }
        __syncthreads();

        // ---- phase 2: tf32 mma, B frags from L1 ----
        float acc[4][2][4];
#pragma unroll
        for (int mt = 0; mt < 4; ++mt)
#pragma unroll
            for (int j = 0; j < 2; ++j)
#pragma unroll
                for (int s = 0; s < 4; ++s) acc[mt][j][s] = 0.0f;

#pragma unroll
        for (int kk = 0; kk < 16; ++kk) {
            const float* wr = W2 + (size_t)(kk * 8 + t) * H;
            unsigned bb0[2], bb1[2];
            bb0[0] = f2tf(__ldg(wr + ncol0));
            bb0[1] = f2tf(__ldg(wr + 4 * H + ncol0));
            bb1[0] = f2tf(__ldg(wr + ncol0 + 8));
            bb1[1] = f2tf(__ldg(wr + 4 * H + ncol0 + 8));
#pragma unroll
            for (int mt = 0; mt < 4; ++mt) {
                float4 av = *(const float4*)(U + (mt * 16 + kk) * FR + lane * 4);
                unsigned a[4] = {__float_as_uint(av.x), __float_as_uint(av.y),
                                 __float_as_uint(av.z), __float_as_uint(av.w)};
                mma_tf32(acc[mt][0], a, bb0);
                mma_tf32(acc[mt][1], a, bb1);
            }
        }
        __syncthreads();   // all warps done reading U before overwrite as Ms

        // ---- phase 3a: silu(m)+bias into smem [edge][col] ----
#pragma unroll
        for (int mt = 0; mt < 4; ++mt) {
            const int e_lo = mt * 16 + g;
            const int e_hi = e_lo + 8;
#pragma unroll
            for (int j = 0; j < 2; ++j) {
                const int col = wn * 16 + j * 8 + t * 2;
                *(float2*)(U + e_lo * MS + col) = make_float2(
                    silu_f(acc[mt][j][0] + b2v[j][0]),
                    silu_f(acc[mt][j][1] + b2v[j][1]));
                *(float2*)(U + e_hi * MS + col) = make_float2(
                    silu_f(acc[mt][j][2] + b2v[j][0]),
                    silu_f(acc[mt][j][3] + b2v[j][1]));
            }
        }
        __syncthreads();

        // ---- phase 3b: segmented flush (8-edge strips, 4 cols/thread) ----
        {
            const int cg4 = (tid & 31) * 4;
            const int strip = tid >> 5;
            float4 a4 = make_float4(0.f, 0.f, 0.f, 0.f);
            int cur = -1;
#pragma unroll
            for (int i = 0; i < 8; ++i) {
                int e = strip * 8 + i;
                if (e >= cnt) break;
                int dd = sdst[e];
                float4 v = *(const float4*)(U + e * MS + cg4);
                if (dd != cur) {
                    if (cur >= 0)
                        red_add_v4(agg + (size_t)cur * H + cg4, a4.x, a4.y, a4.z, a4.w);
                    cur = dd; a4 = v;
                } else {
                    a4.x += v.x; a4.y += v.y; a4.z += v.z; a4.w += v.w;
                }
            }
            if (cur >= 0)
                red_add_v4(agg + (size_t)cur * H + cg4, a4.x, a4.y, a4.z, a4.w);
        }
        __syncthreads();
    }
}

// ---------------- small utility kernels --------------------------------------
__global__ void init_kernel(float* __restrict__ pos, const float* __restrict__ src,
                            float* __restrict__ dpos, int n3) {
    int i = blockIdx.x * blockDim.x + threadIdx.x;
    if (i < n3) { pos[i] = src[i]; dpos[i] = 0.0f; }
}
__global__ void addzero_kernel(float* __restrict__ pos, float* __restrict__ dpos, int n3) {
    int i = blockIdx.x * blockDim.x + threadIdx.x;
    if (i < n3) { pos[i] += dpos[i]; dpos[i] = 0.0f; }
}
__global__ void copy_kernel(float* __restrict__ dst, const float* __restrict__ src, int n) {
    int i = blockIdx.x * blockDim.x + threadIdx.x;
    if (i < n) dst[i] = src[i];
}
// zero agg, init wnode to cb2[0]
__global__ void zero_aw_kernel(float* __restrict__ a, int n1,
                               float* __restrict__ w, int n2,
                               const float* __restrict__ cb2) {
    int i = blockIdx.x * blockDim.x + threadIdx.x;
    if (i < n1) a[i] = 0.0f;
    else if (i - n1 < n2) w[i - n1] = cb2[0];
}

// ---------------- host orchestration -----------------------------------------
extern "C" void kernel_launch(void* const* d_in, const int* in_sizes, int n_in,
                              void* d_out, int out_size)
{
    const float* h_in   = (const float*)d_in[0];
    const float* pos_in = (const float*)d_in[1];
    const int*   ei     = (const int*)d_in[2];
    const float* embW   = (const float*)d_in[3];
    const float* embB   = (const float*)d_in[4];
    const float* msgW1  = (const float*)d_in[5];
    const float* msgB1  = (const float*)d_in[6];
    const float* msgW2  = (const float*)d_in[7];
    const float* msgB2  = (const float*)d_in[8];
    const float* cW1    = (const float*)d_in[9];
    const float* cB1    = (const float*)d_in[10];
    const float* cW2    = (const float*)d_in[11];
    const float* cB2    = (const float*)d_in[12];
    const float* nW1    = (const float*)d_in[13];
    const float* nB1    = (const float*)d_in[14];
    const float* nW2    = (const float*)d_in[15];
    const float* nB2    = (const float*)d_in[16];
    const float* oW1    = (const float*)d_in[17];
    const float* oB1    = (const float*)d_in[18];
    const float* oW2    = (const float*)d_in[19];
    const float* oB2    = (const float*)d_in[20];

    const int N = in_sizes[1] / 3;
    const int E = in_sizes[2] / 2;
    const int Etot = E + N;
    const int INDIM = in_sizes[0] / N;

    float *bh, *bA, *bB, *bagg, *bT, *bpos, *bdpos, *bwn;
    int *bcnt, *bbsum, *bcur, *besrc, *bedst;
    cudaGetSymbolAddress((void**)&bh, g_h);
    cudaGetSymbolAddress((void**)&bA, g_A);
    cudaGetSymbolAddress((void**)&bB, g_B);
    cudaGetSymbolAddress((void**)&bagg, g_agg);
    cudaGetSymbolAddress((void**)&bT, g_T);
    cudaGetSymbolAddress((void**)&bpos, g_pos);
    cudaGetSymbolAddress((void**)&bdpos, g_dpos);
    cudaGetSymbolAddress((void**)&bwn, g_wnode);
    cudaGetSymbolAddress((void**)&bcnt, g_cnt);
    cudaGetSymbolAddress((void**)&bbsum, g_bsum);
    cudaGetSymbolAddress((void**)&bcur, g_cursor);
    cudaGetSymbolAddress((void**)&besrc, g_esrc);
    cudaGetSymbolAddress((void**)&bedst, g_edst);

    const int NODE_SMEM = 64 * FR * 4;
    const int EDGE_SMEM = 64 * FR * 4 + 7 * TE * 4;
    cudaFuncSetAttribute(node_gemm,
                         cudaFuncAttributeMaxDynamicSharedMemorySize, NODE_SMEM);
    cudaFuncSetAttribute(fused3_gemm,
                         cudaFuncAttributeMaxDynamicSharedMemorySize, NODE_SMEM);
    cudaFuncSetAttribute(edge_kernel,
                         cudaFuncAttributeMaxDynamicSharedMemorySize, EDGE_SMEM);

    const int gn = (N + 63) / 64;
    const int t256p = (N * 3 + 255) / 256;
    const int nb = (N + 255) / 256;
    const int ge = (Etot + 255) / 256;

    // ---- sort edges by dst (once; edge_index static across layers) ----
    cudaMemsetAsync(bcnt, 0, (size_t)N * sizeof(int));
    hist_kernel<<<ge, 256>>>(ei, E, Etot, bcnt);
    psum_kernel<<<nb, 256>>>(bcnt, N, bbsum);
    scanb_kernel<<<1, 32>>>(bbsum, nb);
    offs_kernel<<<nb, 256>>>(bcnt, N, bbsum, bcur);
    scatter_kernel<<<ge, 256>>>(ei, E, Etot, bcur, besrc, bedst);

    // ---- embedding + pos init ----
    node_gemm<<<gn, 256, NODE_SMEM>>>(h_in, INDIM, nullptr, 0, embW, embB,
                                      nullptr, 0, bh, N);
    init_kernel<<<t256p, 256>>>(bpos, pos_in, bdpos, N * 3);

    for (int l = 0; l < LAYERS; ++l) {
        const float* W1a = msgW1 + (size_t)l * 257 * H;
        const float* W1b = W1a + 128 * H;
        const float* W1c = msgW1 + (size_t)l * 257 * H + 256 * H;

        zero_aw_kernel<<<(N * H + N + 255) / 256, 256>>>(bagg, N * H, bwn, N, cB2 + l);
        fused3_gemm<<<dim3(gn, 3), 256, NODE_SMEM>>>(
            bh, cW1 + (size_t)l * H * H, cB1 + l * H, cW2 + (size_t)l * H, bwn,
            W1a, W1b, bA, bB, N);

        edge_kernel<<<444, 256, EDGE_SMEM>>>(
            besrc, bedst, Etot, bA, bB, bpos, bwn,
            msgW2 + (size_t)l * H * H, msgB1 + l * H, msgB2 + l * H, W1c,
            bagg, bdpos);

        node_gemm<<<gn, 256, NODE_SMEM>>>(bh, H, bagg, H, nW1 + (size_t)l * 2 * H * H,
                                          nB1 + l * H, nullptr, 1, bT, N);
        node_gemm<<<gn, 256, NODE_SMEM>>>(bT, H, nullptr, 0, nW2 + (size_t)l * H * H,
                                          nB2 + l * H, bh, 0, bh, N);
        addzero_kernel<<<t256p, 256>>>(bpos, bdpos, N * 3);
    }

    node_gemm<<<gn, 256, NODE_SMEM>>>(bh, H, nullptr, 0, oW1, oB1, nullptr, 1, bT, N);
    node_gemm<<<gn, 256, NODE_SMEM>>>(bT, H, nullptr, 0, oW2, oB2, nullptr, 0,
                                      (float*)d_out, N);

    if (out_size >= N * H + N * 3) {
        copy_kernel<<<t256p, 256>>>((float*)d_out + (size_t)N * H, bpos, N * 3);
    }
}

// round 8
// speedup vs baseline: 1.1924x; 1.1924x over previous
#include <cuda_runtime.h>
#include <math.h>

#define H 128
#define LAYERS 4
#define NMAX 50176
#define EPS 1e-8f
#define FR 132   // fragment-pack stride in floats (2-way-conflict choice)

// ---------------- static device scratch (allocation-free rule) ----------------
__device__ float g_h[NMAX * H];
__device__ float g_A[NMAX * H];      // (h @ msgW1[0:128])   -> indexed by dst
__device__ float g_B[NMAX * H];      // (h @ msgW1[128:256]) -> indexed by src
__device__ float g_agg[NMAX * H];    // message scatter target
__device__ float g_T[NMAX * H];      // generic temp
__device__ float g_pos[NMAX * 3];
__device__ float g_dpos[NMAX * 3];
__device__ float g_wnode[NMAX];
__device__ unsigned g_w2pack[LAYERS * 16 * 8 * 32 * 4];  // tf32-frag-packed msgW2

__device__ __forceinline__ float silu_f(float x) {
    return x / (1.0f + __expf(-x));
}

__device__ __forceinline__ unsigned f2tf(float x) {
    unsigned r;
    asm("cvt.rna.tf32.f32 %0, %1;" : "=r"(r) : "f"(x));
    return r;
}

__device__ __forceinline__ void mma_tf32(float c[4], const unsigned a[4], const unsigned b[2]) {
    asm volatile(
        "mma.sync.aligned.m16n8k8.row.col.f32.tf32.tf32.f32 "
        "{%0,%1,%2,%3}, {%4,%5,%6,%7}, {%8,%9}, {%0,%1,%2,%3};"
        : "+f"(c[0]), "+f"(c[1]), "+f"(c[2]), "+f"(c[3])
        : "r"(a[0]), "r"(a[1]), "r"(a[2]), "r"(a[3]), "r"(b[0]), "r"(b[1]));
}

__device__ __forceinline__ void red_add_v4(float* addr, float a, float b, float c, float d) {
    asm volatile("red.global.add.v4.f32 [%0], {%1,%2,%3,%4};"
                 :: "l"(addr), "f"(a), "f"(b), "f"(c), "f"(d) : "memory");
}

// fragment-packed smem address for (row r in 0..63, k in 0..127)
__device__ __forceinline__ int fp_addr(int r, int k) {
    return ((r >> 4) * 16 + (k >> 3)) * FR + ((r & 7) * 4 + (k & 3)) * 4
         + ((r >> 3) & 1) + 2 * ((k >> 2) & 1);
}

// ---------------- W2 fragment pack (all layers, once per launch) --------------
// layout: uint4 per (layer, kk, wn, lane): {b0lo, b0hi, b1lo, b1hi} tf32 bits
__global__ void packw2_kernel(const float* __restrict__ msgW2, unsigned* __restrict__ out) {
    int idx = blockIdx.x * blockDim.x + threadIdx.x;   // 0 .. LAYERS*16*8*32-1
    if (idx >= LAYERS * 16 * 8 * 32) return;
    int l  = idx & 31;
    int wn = (idx >> 5) & 7;
    int kk = (idx >> 8) & 15;
    int ly = idx >> 12;
    int g = l >> 2, t = l & 3;
    int ncol = wn * 16 + g;
    const float* W2 = msgW2 + (size_t)ly * H * H;
    uint4 v;
    v.x = f2tf(W2[(kk * 8 + t) * H + ncol]);
    v.y = f2tf(W2[(kk * 8 + t + 4) * H + ncol]);
    v.z = f2tf(W2[(kk * 8 + t) * H + ncol + 8]);
    v.w = f2tf(W2[(kk * 8 + t + 4) * H + ncol + 8]);
    *(uint4*)(out + (size_t)idx * 4) = v;
}

// ---------------- node-side GEMM (tf32 mma), 64-row tiles, 256 threads --------
template <int KS>
__device__ __forceinline__ void node_chunk64(
    const float* __restrict__ src, int stride, int coff, int kc,
    const float* __restrict__ W,
    float (&d)[4][2][4], float* Xs, int n, int row0)
{
    const int tid = threadIdx.x;
    const int lane = tid & 31;
    const int wn = tid >> 5;
    const int g = lane >> 2, t = lane & 3;

    __syncthreads();
    constexpr int Q4 = KS * 2;
#pragma unroll
    for (int q = tid; q < 64 * Q4; q += 256) {
        int r = q / Q4;
        int kq = (q - r * Q4) << 2;
        int row = row0 + r;
        float4 v = make_float4(0.f, 0.f, 0.f, 0.f);
        if (row < n) v = *(const float4*)(src + (size_t)row * stride + coff + kq);
        float vv[4] = {v.x, v.y, v.z, v.w};
#pragma unroll
        for (int s2 = 0; s2 < 4; ++s2)
            Xs[fp_addr(r, kq + s2)] = __uint_as_float(f2tf(vv[s2]));
    }
    __syncthreads();

    const int ncol0 = wn * 16 + g;
#pragma unroll
    for (int kk = 0; kk < KS; ++kk) {
        const float* wr = W + (size_t)(kc + kk * 8 + t) * H;
        unsigned bb0[2], bb1[2];
        bb0[0] = f2tf(__ldg(wr + ncol0));
        bb0[1] = f2tf(__ldg(wr + 4 * H + ncol0));
        bb1[0] = f2tf(__ldg(wr + ncol0 + 8));
        bb1[1] = f2tf(__ldg(wr + 4 * H + ncol0 + 8));
#pragma unroll
        for (int mt = 0; mt < 4; ++mt) {
            float4 av = *(const float4*)(Xs + (mt * 16 + kk) * FR + lane * 4);
            unsigned a[4] = {__float_as_uint(av.x), __float_as_uint(av.y),
                             __float_as_uint(av.z), __float_as_uint(av.w)};
            mma_tf32(d[mt][0], a, bb0);
            mma_tf32(d[mt][1], a, bb1);
        }
    }
}

// act: 0 = none, 1 = silu, 2 = silu + wnode-dot (no Y store)
__device__ __forceinline__ void gemm_body64(
    const float* __restrict__ X1, int K1,
    const float* __restrict__ X2, int K2,
    const float* __restrict__ W,
    const float* __restrict__ bias,
    const float* __restrict__ res,
    int act,
    float* __restrict__ Y, int n, int row0, float* Xs,
    const float* __restrict__ w2vec, float* __restrict__ wnout,
    float* __restrict__ zero_after)   // if non-null: zero rows [row0,row0+64) at end
{
    const int tid = threadIdx.x;
    const int lane = tid & 31;
    const int wn = tid >> 5;
    const int g = lane >> 2, t = lane & 3;

    float d[4][2][4];
#pragma unroll
    for (int mt = 0; mt < 4; ++mt)
#pragma unroll
        for (int j = 0; j < 2; ++j)
#pragma unroll
            for (int s = 0; s < 4; ++s) d[mt][j][s] = 0.0f;

    const int Ktot = K1 + K2;
    for (int kc = 0; kc < Ktot; kc += 128) {
        const int kchunk = min(128, Ktot - kc);
        const float* src; int stride, coff;
        if (kc < K1) { src = X1; stride = K1; coff = kc; }
        else         { src = X2; stride = K2; coff = kc - K1; }
        if (kchunk == 128) node_chunk64<16>(src, stride, coff, kc, W, d, Xs, n, row0);
        else               node_chunk64<8>(src, stride, coff, kc, W, d, Xs, n, row0);
    }

    if (act == 2) {
        float b0[2], b1v[2], w20[2], w21[2];
#pragma unroll
        for (int j = 0; j < 2; ++j) {
            const int col = wn * 16 + j * 8 + t * 2;
            b0[j] = bias ? bias[col] : 0.0f;
            b1v[j] = bias ? bias[col + 1] : 0.0f;
            w20[j] = w2vec[col];
            w21[j] = w2vec[col + 1];
        }
#pragma unroll
        for (int mt = 0; mt < 4; ++mt) {
#pragma unroll
            for (int half = 0; half < 2; ++half) {
                int row = row0 + mt * 16 + g + half * 8;
                float s = 0.0f;
#pragma unroll
                for (int j = 0; j < 2; ++j) {
                    float o0 = silu_f(d[mt][j][half * 2 + 0] + b0[j]);
                    float o1 = silu_f(d[mt][j][half * 2 + 1] + b1v[j]);
                    s = fmaf(o0, w20[j], fmaf(o1, w21[j], s));
                }
                s += __shfl_xor_sync(0xffffffffu, s, 1);
                s += __shfl_xor_sync(0xffffffffu, s, 2);
                if (t == 0 && row < n) atomicAdd(wnout + row, s);
            }
        }
        return;
    }

#pragma unroll
    for (int j = 0; j < 2; ++j) {
        const int col = wn * 16 + j * 8 + t * 2;
        float b0 = bias ? bias[col] : 0.0f;
        float b1v = bias ? bias[col + 1] : 0.0f;
#pragma unroll
        for (int mt = 0; mt < 4; ++mt) {
#pragma unroll
            for (int half = 0; half < 2; ++half) {
                int row = row0 + mt * 16 + g + half * 8;
                if (row < n) {
                    float o0 = d[mt][j][half * 2 + 0] + b0;
                    float o1 = d[mt][j][half * 2 + 1] + b1v;
                    if (act == 1) { o0 = silu_f(o0); o1 = silu_f(o1); }
                    if (res) {
                        o0 += res[(size_t)row * H + col];
                        o1 += res[(size_t)row * H + col + 1];
                    }
                    *(float2*)(Y + (size_t)row * H + col) = make_float2(o0, o1);
                }
            }
        }
    }

    // fused zeroing of consumed scatter buffer rows (race-free: only this
    // block read these rows as X2, and only this block writes them here)
    if (zero_after) {
        const float4 z = make_float4(0.f, 0.f, 0.f, 0.f);
#pragma unroll
        for (int q = tid; q < 64 * 32; q += 256) {
            int r = q >> 5, c4 = q & 31;
            int row = row0 + r;
            if (row < n) *(float4*)(zero_after + (size_t)row * H + c4 * 4) = z;
        }
    }
}

__global__ __launch_bounds__(256, 3) void node_gemm(
    const float* __restrict__ X1, int K1,
    const float* __restrict__ X2, int K2,
    const float* __restrict__ W,
    const float* __restrict__ bias,
    const float* __restrict__ res,
    int act,
    float* __restrict__ Y, int n,
    float* __restrict__ zero_after)
{
    extern __shared__ float Xs[];
    gemm_body64(X1, K1, X2, K2, W, bias, res, act, Y, n, blockIdx.x * 64, Xs,
                nullptr, nullptr, zero_after);
}

// one launch: wnode (via cW1/cW2 dot, atomic), A = h@W1a, B = h@W1b
__global__ __launch_bounds__(256, 3) void fused3_gemm(
    const float* __restrict__ hbuf,
    const float* __restrict__ cW1, const float* __restrict__ cB1,
    const float* __restrict__ cW2, float* __restrict__ wn,
    const float* __restrict__ W1a, const float* __restrict__ W1b,
    float* __restrict__ A, float* __restrict__ B, int n)
{
    extern __shared__ float Xs[];
    if (blockIdx.y == 0) {
        gemm_body64(hbuf, H, nullptr, 0, cW1, cB1, nullptr, 2, nullptr, n,
                    blockIdx.x * 64, Xs, cW2, wn, nullptr);
    } else if (blockIdx.y == 1) {
        gemm_body64(hbuf, H, nullptr, 0, W1a, nullptr, nullptr, 0, A, n,
                    blockIdx.x * 64, Xs, nullptr, nullptr, nullptr);
    } else {
        gemm_body64(hbuf, H, nullptr, 0, W1b, nullptr, nullptr, 0, B, n,
                    blockIdx.x * 64, Xs, nullptr, nullptr, nullptr);
    }
}

// ---------------- fused edge kernel (tf32 mma, 64-edge tiles, 256 threads) ----
#define TE 64
__global__ __launch_bounds__(256, 3) void edge_kernel(
    const int* __restrict__ ei, int E, int Etot,
    const float* __restrict__ A, const float* __restrict__ B,
    const float* __restrict__ pos, const float* __restrict__ wnode,
    const unsigned* __restrict__ W2p, const float* __restrict__ b1,
    const float* __restrict__ b2, const float* __restrict__ w1c,
    float* __restrict__ agg, float* __restrict__ dpos)
{
    extern __shared__ float smbuf[];
    float* U = smbuf;                    // 64 frags * FR floats
    float* sdist = U + 64 * FR;          // 64
    int* ssrc = (int*)(sdist + TE);      // 64
    int* sdst = ssrc + TE;               // 64

    const int tid = threadIdx.x;
    const int lane = tid & 31;
    const int wn = tid >> 5;             // 8 warps = 8 col groups of 16
    const int g = lane >> 2, t = lane & 3;

    const int fq = lane;
    const int eg = wn;
    const float4 w1c4 = *(const float4*)(w1c + fq * 4);
    const float4 b1_4 = *(const float4*)(b1 + fq * 4);
    const int fragk = fq >> 1;
    const int slot2 = 2 * (fq & 1);
    float b2v[2][2];
#pragma unroll
    for (int j = 0; j < 2; ++j) {
        b2v[j][0] = b2[wn * 16 + j * 8 + t * 2];
        b2v[j][1] = b2[wn * 16 + j * 8 + t * 2 + 1];
    }
    // packed W2 base for this warp/lane: one uint4 per kk
    const uint4* wp = (const uint4*)W2p + (size_t)wn * 32 + lane;

    const int ntiles = (Etot + TE - 1) / TE;
    for (int tile = blockIdx.x; tile < ntiles; tile += gridDim.x) {
        const int e0 = tile * TE;
        const int cnt = min(TE, Etot - e0);

        // ---- meta + coord update ----
        if (tid < TE) {
            int e = e0 + tid;
            int s = 0, dd = 0; float dist = 0.f;
            if (tid < cnt) {
                float rx, ry, rz;
                if (e < E) { s = ei[e]; dd = ei[E + e]; }
                else       { s = e - E; dd = s; }
                rx = pos[s * 3 + 0] - pos[dd * 3 + 0];
                ry = pos[s * 3 + 1] - pos[dd * 3 + 1];
                rz = pos[s * 3 + 2] - pos[dd * 3 + 2];
                dist = sqrtf(rx * rx + ry * ry + rz * rz);
                float inv = wnode[s] / (dist + EPS);
                atomicAdd(dpos + dd * 3 + 0, rx * inv);
                atomicAdd(dpos + dd * 3 + 1, ry * inv);
                atomicAdd(dpos + dd * 3 + 2, rz * inv);
            }
            ssrc[tid] = s; sdst[tid] = dd; sdist[tid] = dist;
        }
        __syncthreads();

        // ---- phase 1: u via LDG.128 gathers (4 features x 8 edges / thread) --
#pragma unroll
        for (int i = 0; i < 8; ++i) {
            int e = eg * 8 + i;
            int s = ssrc[e], dd = sdst[e];
            float dist = sdist[e];
            float4 a4 = *(const float4*)(A + (size_t)dd * H + fq * 4);
            float4 c4 = *(const float4*)(B + (size_t)s * H + fq * 4);
            int base0 = ((e >> 4) * 16 + fragk) * FR + (e & 7) * 16
                      + ((e >> 3) & 1) + slot2;
            U[base0 + 0]  = __uint_as_float(f2tf(silu_f(a4.x + c4.x + dist * w1c4.x + b1_4.x)));
            U[base0 + 4]  = __uint_as_float(f2tf(silu_f(a4.y + c4.y + dist * w1c4.y + b1_4.y)));
            U[base0 + 8]  = __uint_as_float(f2tf(silu_f(a4.z + c4.z + dist * w1c4.z + b1_4.z)));
            U[base0 + 12] = __uint_as_float(f2tf(silu_f(a4.w + c4.w + dist * w1c4.w + b1_4.w)));
        }
        __syncthreads();

        // ---- phase 2: tf32 mma, packed B via single LDG.128 per kk ----
        float acc[4][2][4];
#pragma unroll
        for (int mt = 0; mt < 4; ++mt)
#pragma unroll
            for (int j = 0; j < 2; ++j)
#pragma unroll
                for (int s = 0; s < 4; ++s) acc[mt][j][s] = 0.0f;

#pragma unroll
        for (int kk = 0; kk < 16; ++kk) {
            uint4 bv = __ldg(wp + (size_t)kk * 256);   // (kk*8+wn)*32+lane
            unsigned bb0[2] = {bv.x, bv.y};
            unsigned bb1[2] = {bv.z, bv.w};
#pragma unroll
            for (int mt = 0; mt < 4; ++mt) {
                float4 av = *(const float4*)(U + (mt * 16 + kk) * FR + lane * 4);
                unsigned a[4] = {__float_as_uint(av.x), __float_as_uint(av.y),
                                 __float_as_uint(av.z), __float_as_uint(av.w)};
                mma_tf32(acc[mt][0], a, bb0);
                mma_tf32(acc[mt][1], a, bb1);
            }
        }

        // ---- phase 3: silu + shuffle-paired v4 scatter ----
#pragma unroll
        for (int mt = 0; mt < 4; ++mt) {
            const int e_lo = mt * 16 + g;
            const int e_hi = e_lo + 8;
#pragma unroll
            for (int j = 0; j < 2; ++j) {
                float v0 = silu_f(acc[mt][j][0] + b2v[j][0]);
                float v1 = silu_f(acc[mt][j][1] + b2v[j][1]);
                float v2 = silu_f(acc[mt][j][2] + b2v[j][0]);
                float v3 = silu_f(acc[mt][j][3] + b2v[j][1]);
                float w0 = __shfl_xor_sync(0xffffffffu, v0, 1);
                float w1 = __shfl_xor_sync(0xffffffffu, v1, 1);
                float w2 = __shfl_xor_sync(0xffffffffu, v2, 1);
                float w3 = __shfl_xor_sync(0xffffffffu, v3, 1);
                if ((t & 1) == 0) {
                    const int col4 = wn * 16 + j * 8 + t * 2;
                    if (e_lo < cnt)
                        red_add_v4(agg + (size_t)sdst[e_lo] * H + col4, v0, v1, w0, w1);
                    if (e_hi < cnt)
                        red_add_v4(agg + (size_t)sdst[e_hi] * H + col4, v2, v3, w2, w3);
                }
            }
        }
        __syncthreads();
    }
}

// ---------------- small utility kernels --------------------------------------
__global__ void init_kernel(float* __restrict__ pos, const float* __restrict__ src,
                            float* __restrict__ dpos, int n3,
                            float* __restrict__ agg, int nagg) {
    int i = blockIdx.x * blockDim.x + threadIdx.x;
    if (i < n3) { pos[i] = src[i]; dpos[i] = 0.0f; }
    if (i < nagg) agg[i] = 0.0f;
}
__global__ void addzero_kernel(float* __restrict__ pos, float* __restrict__ dpos, int n3) {
    int i = blockIdx.x * blockDim.x + threadIdx.x;
    if (i < n3) { pos[i] += dpos[i]; dpos[i] = 0.0f; }
}
__global__ void copy_kernel(float* __restrict__ dst, const float* __restrict__ src, int n) {
    int i = blockIdx.x * blockDim.x + threadIdx.x;
    if (i < n) dst[i] = src[i];
}
__global__ void initw_kernel(float* __restrict__ w, int n, const float* __restrict__ cb2) {
    int i = blockIdx.x * blockDim.x + threadIdx.x;
    if (i < n) w[i] = cb2[0];
}

// ---------------- host orchestration -----------------------------------------
extern "C" void kernel_launch(void* const* d_in, const int* in_sizes, int n_in,
                              void* d_out, int out_size)
{
    const float* h_in   = (const float*)d_in[0];
    const float* pos_in = (const float*)d_in[1];
    const int*   ei     = (const int*)d_in[2];
    const float* embW   = (const float*)d_in[3];
    const float* embB   = (const float*)d_in[4];
    const float* msgW1  = (const float*)d_in[5];
    const float* msgB1  = (const float*)d_in[6];
    const float* msgW2  = (const float*)d_in[7];
    const float* msgB2  = (const float*)d_in[8];
    const float* cW1    = (const float*)d_in[9];
    const float* cB1    = (const float*)d_in[10];
    const float* cW2    = (const float*)d_in[11];
    const float* cB2    = (const float*)d_in[12];
    const float* nW1    = (const float*)d_in[13];
    const float* nB1    = (const float*)d_in[14];
    const float* nW2    = (const float*)d_in[15];
    const float* nB2    = (const float*)d_in[16];
    const float* oW1    = (const float*)d_in[17];
    const float* oB1    = (const float*)d_in[18];
    const float* oW2    = (const float*)d_in[19];
    const float* oB2    = (const float*)d_in[20];

    const int N = in_sizes[1] / 3;
    const int E = in_sizes[2] / 2;
    const int Etot = E + N;
    const int INDIM = in_sizes[0] / N;

    float *bh, *bA, *bB, *bagg, *bT, *bpos, *bdpos, *bwn;
    unsigned* bw2p;
    cudaGetSymbolAddress((void**)&bh, g_h);
    cudaGetSymbolAddress((void**)&bA, g_A);
    cudaGetSymbolAddress((void**)&bB, g_B);
    cudaGetSymbolAddress((void**)&bagg, g_agg);
    cudaGetSymbolAddress((void**)&bT, g_T);
    cudaGetSymbolAddress((void**)&bpos, g_pos);
    cudaGetSymbolAddress((void**)&bdpos, g_dpos);
    cudaGetSymbolAddress((void**)&bwn, g_wnode);
    cudaGetSymbolAddress((void**)&bw2p, g_w2pack);

    const int NODE_SMEM = 64 * FR * 4;                 // 33792 B
    const int EDGE_SMEM = 64 * FR * 4 + 3 * TE * 4;    // + meta
    cudaFuncSetAttribute(node_gemm,
                         cudaFuncAttributeMaxDynamicSharedMemorySize, NODE_SMEM);
    cudaFuncSetAttribute(fused3_gemm,
                         cudaFuncAttributeMaxDynamicSharedMemorySize, NODE_SMEM);
    cudaFuncSetAttribute(edge_kernel,
                         cudaFuncAttributeMaxDynamicSharedMemorySize, EDGE_SMEM);

    const int gn = (N + 63) / 64;
    const int tinit = (N * H + 255) / 256;
    const int t256p = (N * 3 + 255) / 256;

    // pack all layers' msgW2 into tf32 MMA-fragment order (once)
    packw2_kernel<<<(LAYERS * 16 * 8 * 32 + 255) / 256, 256>>>(msgW2, bw2p);

    // embedding + pos/dpos/agg init
    node_gemm<<<gn, 256, NODE_SMEM>>>(h_in, INDIM, nullptr, 0, embW, embB,
                                      nullptr, 0, bh, N, nullptr);
    init_kernel<<<tinit, 256>>>(bpos, pos_in, bdpos, N * 3, bagg, N * H);

    for (int l = 0; l < LAYERS; ++l) {
        const float* W1a = msgW1 + (size_t)l * 257 * H;
        const float* W1b = W1a + 128 * H;
        const float* W1c = msgW1 + (size_t)l * 257 * H + 256 * H;

        initw_kernel<<<(N + 255) / 256, 256>>>(bwn, N, cB2 + l);
        fused3_gemm<<<dim3(gn, 3), 256, NODE_SMEM>>>(
            bh, cW1 + (size_t)l * H * H, cB1 + l * H, cW2 + (size_t)l * H, bwn,
            W1a, W1b, bA, bB, N);

        edge_kernel<<<444, 256, EDGE_SMEM>>>(
            ei, E, Etot, bA, bB, bpos, bwn,
            bw2p + (size_t)l * 16 * 8 * 32 * 4, msgB1 + l * H, msgB2 + l * H, W1c,
            bagg, bdpos);

        // node update; fused: zero agg rows after consumption
        node_gemm<<<gn, 256, NODE_SMEM>>>(bh, H, bagg, H, nW1 + (size_t)l * 2 * H * H,
                                          nB1 + l * H, nullptr, 1, bT, N, bagg);
        node_gemm<<<gn, 256, NODE_SMEM>>>(bT, H, nullptr, 0, nW2 + (size_t)l * H * H,
                                          nB2 + l * H, bh, 0, bh, N, nullptr);
        addzero_kernel<<<t256p, 256>>>(bpos, bdpos, N * 3);
    }

    node_gemm<<<gn, 256, NODE_SMEM>>>(bh, H, nullptr, 0, oW1, oB1, nullptr, 1,
                                      bT, N, nullptr);
    node_gemm<<<gn, 256, NODE_SMEM>>>(bT, H, nullptr, 0, oW2, oB2, nullptr, 0,
                                      (float*)d_out, N, nullptr);

    if (out_size >= N * H + N * 3) {
        copy_kernel<<<t256p, 256>>>((float*)d_out + (size_t)N * H, bpos, N * 3);
    }
}

// round 9
// speedup vs baseline: 1.2767x; 1.0707x over previous
#include <cuda_runtime.h>
#include <math.h>

#define H 128
#define LAYERS 4
#define NMAX 50176
#define EPS 1e-8f
#define FR 132   // fragment-pack stride in floats (2-way-conflict choice)

// ---------------- static device scratch (allocation-free rule) ----------------
__device__ float g_h[NMAX * H];
__device__ float g_A[NMAX * H];      // (h @ msgW1[0:128])   -> indexed by dst
__device__ float g_B[NMAX * H];      // (h @ msgW1[128:256]) -> indexed by src
__device__ float g_agg[NMAX * H];    // message scatter target
__device__ float g_T[NMAX * H];      // generic temp
__device__ float g_pos[NMAX * 3];
__device__ float g_dpos[NMAX * 3];
__device__ float g_wnode[NMAX];
__device__ unsigned g_wpack[560000]; // tf32-frag-packed weights (uint4-aligned)

__device__ __forceinline__ float silu_f(float x) {
    return x / (1.0f + __expf(-x));
}

__device__ __forceinline__ unsigned f2tf(float x) {
    unsigned r;
    asm("cvt.rna.tf32.f32 %0, %1;" : "=r"(r) : "f"(x));
    return r;
}

__device__ __forceinline__ void mma_tf32(float c[4], const unsigned a[4], const unsigned b[2]) {
    asm volatile(
        "mma.sync.aligned.m16n8k8.row.col.f32.tf32.tf32.f32 "
        "{%0,%1,%2,%3}, {%4,%5,%6,%7}, {%8,%9}, {%0,%1,%2,%3};"
        : "+f"(c[0]), "+f"(c[1]), "+f"(c[2]), "+f"(c[3])
        : "r"(a[0]), "r"(a[1]), "r"(a[2]), "r"(a[3]), "r"(b[0]), "r"(b[1]));
}

__device__ __forceinline__ void red_add_v4(float* addr, float a, float b, float c, float d) {
    asm volatile("red.global.add.v4.f32 [%0], {%1,%2,%3,%4};"
                 :: "l"(addr), "f"(a), "f"(b), "f"(c), "f"(d) : "memory");
}

// fragment-packed smem address for (row r in 0..63, k in 0..127)
__device__ __forceinline__ int fp_addr(int r, int k) {
    return ((r >> 4) * 16 + (k >> 3)) * FR + ((r & 7) * 4 + (k & 3)) * 4
         + ((r >> 3) & 1) + 2 * ((k >> 2) & 1);
}

// ---------------- generic weight fragment pack (once per launch) --------------
// layout per matrix: uint4 per (kk, wn, lane) = {b0lo, b0hi, b1lo, b1hi}
struct PackJobs {
    const float* src[28];
    unsigned dstOff[28];   // in uint4 units
    int blockOff[29];      // one block = one kk (256 threads)
    int njobs;
};

__global__ void packw_kernel(PackJobs jobs, unsigned* __restrict__ out) {
    int b = blockIdx.x;
    int j = 0;
    while (j + 1 < jobs.njobs && b >= jobs.blockOff[j + 1]) ++j;
    int kk = b - jobs.blockOff[j];
    const float* W = jobs.src[j];
    int tid = threadIdx.x;
    int wn = tid >> 5, lane = tid & 31;
    int g = lane >> 2, t = lane & 3;
    int ncol = wn * 16 + g;
    uint4 v;
    v.x = f2tf(W[(kk * 8 + t) * H + ncol]);
    v.y = f2tf(W[(kk * 8 + t + 4) * H + ncol]);
    v.z = f2tf(W[(kk * 8 + t) * H + ncol + 8]);
    v.w = f2tf(W[(kk * 8 + t + 4) * H + ncol + 8]);
    *(uint4*)(out + ((size_t)jobs.dstOff[j] + kk * 256 + wn * 32 + lane) * 4) = v;
}

// ---------------- node-side GEMM (tf32 mma), 64-row tiles, 256 threads --------
template <int KS>
__device__ __forceinline__ void node_chunk64(
    const float* __restrict__ src, int stride, int coff, int kc,
    const uint4* __restrict__ Wp,
    float (&d)[4][2][4], float* Xs, int n, int row0)
{
    const int tid = threadIdx.x;
    const int lane = tid & 31;
    const int wn = tid >> 5;

    __syncthreads();
    constexpr int Q4 = KS * 2;
#pragma unroll
    for (int q = tid; q < 64 * Q4; q += 256) {
        int r = q / Q4;
        int kq = (q - r * Q4) << 2;
        int row = row0 + r;
        float4 v = make_float4(0.f, 0.f, 0.f, 0.f);
        if (row < n) v = *(const float4*)(src + (size_t)row * stride + coff + kq);
        float vv[4] = {v.x, v.y, v.z, v.w};
#pragma unroll
        for (int s2 = 0; s2 < 4; ++s2)
            Xs[fp_addr(r, kq + s2)] = __uint_as_float(f2tf(vv[s2]));
    }
    __syncthreads();

    const uint4* wp = Wp + ((size_t)(kc >> 3) * 8 + wn) * 32 + lane;
#pragma unroll
    for (int kk = 0; kk < KS; ++kk) {
        uint4 bv = __ldg(wp + (size_t)kk * 256);
        unsigned bb0[2] = {bv.x, bv.y};
        unsigned bb1[2] = {bv.z, bv.w};
#pragma unroll
        for (int mt = 0; mt < 4; ++mt) {
            float4 av = *(const float4*)(Xs + (mt * 16 + kk) * FR + lane * 4);
            unsigned a[4] = {__float_as_uint(av.x), __float_as_uint(av.y),
                             __float_as_uint(av.z), __float_as_uint(av.w)};
            mma_tf32(d[mt][0], a, bb0);
            mma_tf32(d[mt][1], a, bb1);
        }
    }
}

// act: 0 = none, 1 = silu, 2 = silu + wnode-dot via smem reduce (no Y store)
__device__ __forceinline__ void gemm_body64(
    const float* __restrict__ X1, int K1,
    const float* __restrict__ X2, int K2,
    const uint4* __restrict__ Wp,
    const float* __restrict__ bias,
    const float* __restrict__ res,
    int act,
    float* __restrict__ Y, int n, int row0, float* Xs,
    const float* __restrict__ w2vec, float* __restrict__ wnout,
    const float* __restrict__ cb2,
    float* __restrict__ zero_after)   // if non-null: zero rows [row0,row0+64) at end
{
    const int tid = threadIdx.x;
    const int lane = tid & 31;
    const int wn = tid >> 5;
    const int g = lane >> 2, t = lane & 3;

    float d[4][2][4];
#pragma unroll
    for (int mt = 0; mt < 4; ++mt)
#pragma unroll
        for (int j = 0; j < 2; ++j)
#pragma unroll
            for (int s = 0; s < 4; ++s) d[mt][j][s] = 0.0f;

    const int Ktot = K1 + K2;
    for (int kc = 0; kc < Ktot; kc += 128) {
        const int kchunk = min(128, Ktot - kc);
        const float* src; int stride, coff;
        if (kc < K1) { src = X1; stride = K1; coff = kc; }
        else         { src = X2; stride = K2; coff = kc - K1; }
        if (kchunk == 128) node_chunk64<16>(src, stride, coff, kc, Wp, d, Xs, n, row0);
        else               node_chunk64<8>(src, stride, coff, kc, Wp, d, Xs, n, row0);
    }

    if (act == 2) {
        // silu + dot with w2vec; cross-warp smem reduce; plain store.
        float b0[2], b1v[2], w20[2], w21[2];
#pragma unroll
        for (int j = 0; j < 2; ++j) {
            const int col = wn * 16 + j * 8 + t * 2;
            b0[j] = bias ? bias[col] : 0.0f;
            b1v[j] = bias ? bias[col + 1] : 0.0f;
            w20[j] = w2vec[col];
            w21[j] = w2vec[col + 1];
        }
        __syncthreads();   // done reading Xs as fragments; reuse as reduce pad
#pragma unroll
        for (int mt = 0; mt < 4; ++mt) {
#pragma unroll
            for (int half = 0; half < 2; ++half) {
                int rl = mt * 16 + g + half * 8;
                float s = 0.0f;
#pragma unroll
                for (int j = 0; j < 2; ++j) {
                    float o0 = silu_f(d[mt][j][half * 2 + 0] + b0[j]);
                    float o1 = silu_f(d[mt][j][half * 2 + 1] + b1v[j]);
                    s = fmaf(o0, w20[j], fmaf(o1, w21[j], s));
                }
                s += __shfl_xor_sync(0xffffffffu, s, 1);
                s += __shfl_xor_sync(0xffffffffu, s, 2);
                if (t == 0) Xs[rl * 8 + wn] = s;
            }
        }
        __syncthreads();
        if (tid < 64) {
            float acc = cb2[0];
#pragma unroll
            for (int w = 0; w < 8; ++w) acc += Xs[tid * 8 + w];
            int row = row0 + tid;
            if (row < n) wnout[row] = acc;
        }
        return;
    }

#pragma unroll
    for (int j = 0; j < 2; ++j) {
        const int col = wn * 16 + j * 8 + t * 2;
        float b0 = bias ? bias[col] : 0.0f;
        float b1v = bias ? bias[col + 1] : 0.0f;
#pragma unroll
        for (int mt = 0; mt < 4; ++mt) {
#pragma unroll
            for (int half = 0; half < 2; ++half) {
                int row = row0 + mt * 16 + g + half * 8;
                if (row < n) {
                    float o0 = d[mt][j][half * 2 + 0] + b0;
                    float o1 = d[mt][j][half * 2 + 1] + b1v;
                    if (act == 1) { o0 = silu_f(o0); o1 = silu_f(o1); }
                    if (res) {
                        o0 += res[(size_t)row * H + col];
                        o1 += res[(size_t)row * H + col + 1];
                    }
                    *(float2*)(Y + (size_t)row * H + col) = make_float2(o0, o1);
                }
            }
        }
    }

    // fused zeroing of consumed scatter buffer rows (race-free)
    if (zero_after) {
        const float4 z = make_float4(0.f, 0.f, 0.f, 0.f);
#pragma unroll
        for (int q = tid; q < 64 * 32; q += 256) {
            int r = q >> 5, c4 = q & 31;
            int row = row0 + r;
            if (row < n) *(float4*)(zero_after + (size_t)row * H + c4 * 4) = z;
        }
    }
}

__global__ __launch_bounds__(256, 3) void node_gemm(
    const float* __restrict__ X1, int K1,
    const float* __restrict__ X2, int K2,
    const uint4* __restrict__ Wp,
    const float* __restrict__ bias,
    const float* __restrict__ res,
    int act,
    float* __restrict__ Y, int n,
    float* __restrict__ zero_after)
{
    extern __shared__ float Xs[];
    gemm_body64(X1, K1, X2, K2, Wp, bias, res, act, Y, n, blockIdx.x * 64, Xs,
                nullptr, nullptr, nullptr, zero_after);
}

// one launch: wnode (via cW1/cW2 dot), A = h@W1a, B = h@W1b
__global__ __launch_bounds__(256, 3) void fused3_gemm(
    const float* __restrict__ hbuf,
    const uint4* __restrict__ cW1p, const float* __restrict__ cB1,
    const float* __restrict__ cW2, const float* __restrict__ cb2,
    float* __restrict__ wn,
    const uint4* __restrict__ W1ap, const uint4* __restrict__ W1bp,
    float* __restrict__ A, float* __restrict__ B, int n)
{
    extern __shared__ float Xs[];
    if (blockIdx.y == 0) {
        gemm_body64(hbuf, H, nullptr, 0, cW1p, cB1, nullptr, 2, nullptr, n,
                    blockIdx.x * 64, Xs, cW2, wn, cb2, nullptr);
    } else if (blockIdx.y == 1) {
        gemm_body64(hbuf, H, nullptr, 0, W1ap, nullptr, nullptr, 0, A, n,
                    blockIdx.x * 64, Xs, nullptr, nullptr, nullptr, nullptr);
    } else {
        gemm_body64(hbuf, H, nullptr, 0, W1bp, nullptr, nullptr, 0, B, n,
                    blockIdx.x * 64, Xs, nullptr, nullptr, nullptr, nullptr);
    }
}

// ---------------- fused edge kernel (tf32 mma, 64-edge tiles, 256 threads) ----
#define TE 64
__global__ __launch_bounds__(256, 3) void edge_kernel(
    const int* __restrict__ ei, int E, int Etot,
    const float* __restrict__ A, const float* __restrict__ B,
    const float* __restrict__ pos, const float* __restrict__ wnode,
    const unsigned* __restrict__ W2p, const float* __restrict__ b1,
    const float* __restrict__ b2, const float* __restrict__ w1c,
    float* __restrict__ agg, float* __restrict__ dpos)
{
    extern __shared__ float smbuf[];
    float* U = smbuf;                    // 64 frags * FR floats
    float* sdist = U + 64 * FR;          // 64
    int* ssrc = (int*)(sdist + TE);      // 64
    int* sdst = ssrc + TE;               // 64

    const int tid = threadIdx.x;
    const int lane = tid & 31;
    const int wn = tid >> 5;             // 8 warps = 8 col groups of 16
    const int g = lane >> 2, t = lane & 3;

    const int fq = lane;
    const int eg = wn;
    const float4 w1c4 = *(const float4*)(w1c + fq * 4);
    const float4 b1_4 = *(const float4*)(b1 + fq * 4);
    const int fragk = fq >> 1;
    const int slot2 = 2 * (fq & 1);
    float b2v[2][2];
#pragma unroll
    for (int j = 0; j < 2; ++j) {
        b2v[j][0] = b2[wn * 16 + j * 8 + t * 2];
        b2v[j][1] = b2[wn * 16 + j * 8 + t * 2 + 1];
    }
    const uint4* wp = (const uint4*)W2p + (size_t)wn * 32 + lane;

    const int ntiles = (Etot + TE - 1) / TE;
    for (int tile = blockIdx.x; tile < ntiles; tile += gridDim.x) {
        const int e0 = tile * TE;
        const int cnt = min(TE, Etot - e0);

        // ---- meta + coord update ----
        if (tid < TE) {
            int e = e0 + tid;
            int s = 0, dd = 0; float dist = 0.f;
            if (tid < cnt) {
                float rx, ry, rz;
                if (e < E) { s = ei[e]; dd = ei[E + e]; }
                else       { s = e - E; dd = s; }
                rx = pos[s * 3 + 0] - pos[dd * 3 + 0];
                ry = pos[s * 3 + 1] - pos[dd * 3 + 1];
                rz = pos[s * 3 + 2] - pos[dd * 3 + 2];
                dist = sqrtf(rx * rx + ry * ry + rz * rz);
                float inv = wnode[s] / (dist + EPS);
                atomicAdd(dpos + dd * 3 + 0, rx * inv);
                atomicAdd(dpos + dd * 3 + 1, ry * inv);
                atomicAdd(dpos + dd * 3 + 2, rz * inv);
            }
            ssrc[tid] = s; sdst[tid] = dd; sdist[tid] = dist;
        }
        __syncthreads();

        // ---- phase 1: u via LDG.128 gathers (4 features x 8 edges / thread) --
#pragma unroll
        for (int i = 0; i < 8; ++i) {
            int e = eg * 8 + i;
            int s = ssrc[e], dd = sdst[e];
            float dist = sdist[e];
            float4 a4 = *(const float4*)(A + (size_t)dd * H + fq * 4);
            float4 c4 = *(const float4*)(B + (size_t)s * H + fq * 4);
            int base0 = ((e >> 4) * 16 + fragk) * FR + (e & 7) * 16
                      + ((e >> 3) & 1) + slot2;
            U[base0 + 0]  = __uint_as_float(f2tf(silu_f(a4.x + c4.x + dist * w1c4.x + b1_4.x)));
            U[base0 + 4]  = __uint_as_float(f2tf(silu_f(a4.y + c4.y + dist * w1c4.y + b1_4.y)));
            U[base0 + 8]  = __uint_as_float(f2tf(silu_f(a4.z + c4.z + dist * w1c4.z + b1_4.z)));
            U[base0 + 12] = __uint_as_float(f2tf(silu_f(a4.w + c4.w + dist * w1c4.w + b1_4.w)));
        }
        __syncthreads();

        // ---- phase 2: tf32 mma, packed B via single LDG.128 per kk ----
        float acc[4][2][4];
#pragma unroll
        for (int mt = 0; mt < 4; ++mt)
#pragma unroll
            for (int j = 0; j < 2; ++j)
#pragma unroll
                for (int s = 0; s < 4; ++s) acc[mt][j][s] = 0.0f;

#pragma unroll
        for (int kk = 0; kk < 16; ++kk) {
            uint4 bv = __ldg(wp + (size_t)kk * 256);
            unsigned bb0[2] = {bv.x, bv.y};
            unsigned bb1[2] = {bv.z, bv.w};
#pragma unroll
            for (int mt = 0; mt < 4; ++mt) {
                float4 av = *(const float4*)(U + (mt * 16 + kk) * FR + lane * 4);
                unsigned a[4] = {__float_as_uint(av.x), __float_as_uint(av.y),
                                 __float_as_uint(av.z), __float_as_uint(av.w)};
                mma_tf32(acc[mt][0], a, bb0);
                mma_tf32(acc[mt][1], a, bb1);
            }
        }

        // ---- phase 3: silu + shuffle-paired v4 scatter ----
#pragma unroll
        for (int mt = 0; mt < 4; ++mt) {
            const int e_lo = mt * 16 + g;
            const int e_hi = e_lo + 8;
#pragma unroll
            for (int j = 0; j < 2; ++j) {
                float v0 = silu_f(acc[mt][j][0] + b2v[j][0]);
                float v1 = silu_f(acc[mt][j][1] + b2v[j][1]);
                float v2 = silu_f(acc[mt][j][2] + b2v[j][0]);
                float v3 = silu_f(acc[mt][j][3] + b2v[j][1]);
                float w0 = __shfl_xor_sync(0xffffffffu, v0, 1);
                float w1 = __shfl_xor_sync(0xffffffffu, v1, 1);
                float w2 = __shfl_xor_sync(0xffffffffu, v2, 1);
                float w3 = __shfl_xor_sync(0xffffffffu, v3, 1);
                if ((t & 1) == 0) {
                    const int col4 = wn * 16 + j * 8 + t * 2;
                    if (e_lo < cnt)
                        red_add_v4(agg + (size_t)sdst[e_lo] * H + col4, v0, v1, w0, w1);
                    if (e_hi < cnt)
                        red_add_v4(agg + (size_t)sdst[e_hi] * H + col4, v2, v3, w2, w3);
                }
            }
        }
        __syncthreads();
    }
}

// ---------------- small utility kernels --------------------------------------
__global__ void init_kernel(float* __restrict__ pos, const float* __restrict__ src,
                            float* __restrict__ dpos, int n3,
                            float* __restrict__ agg, int nagg) {
    int i = blockIdx.x * blockDim.x + threadIdx.x;
    if (i < n3) { pos[i] = src[i]; dpos[i] = 0.0f; }
    if (i < nagg) agg[i] = 0.0f;
}
__global__ void addzero_kernel(float* __restrict__ pos, float* __restrict__ dpos, int n3) {
    int i = blockIdx.x * blockDim.x + threadIdx.x;
    if (i < n3) { pos[i] += dpos[i]; dpos[i] = 0.0f; }
}
__global__ void copy_kernel(float* __restrict__ dst, const float* __restrict__ src, int n) {
    int i = blockIdx.x * blockDim.x + threadIdx.x;
    if (i < n) dst[i] = src[i];
}

// ---------------- host orchestration -----------------------------------------
extern "C" void kernel_launch(void* const* d_in, const int* in_sizes, int n_in,
                              void* d_out, int out_size)
{
    const float* h_in   = (const float*)d_in[0];
    const float* pos_in = (const float*)d_in[1];
    const int*   ei     = (const int*)d_in[2];
    const float* embW   = (const float*)d_in[3];
    const float* embB   = (const float*)d_in[4];
    const float* msgW1  = (const float*)d_in[5];
    const float* msgB1  = (const float*)d_in[6];
    const float* msgW2  = (const float*)d_in[7];
    const float* msgB2  = (const float*)d_in[8];
    const float* cW1    = (const float*)d_in[9];
    const float* cB1    = (const float*)d_in[10];
    const float* cW2    = (const float*)d_in[11];
    const float* cB2    = (const float*)d_in[12];
    const float* nW1    = (const float*)d_in[13];
    const float* nB1    = (const float*)d_in[14];
    const float* nW2    = (const float*)d_in[15];
    const float* nB2    = (const float*)d_in[16];
    const float* oW1    = (const float*)d_in[17];
    const float* oB1    = (const float*)d_in[18];
    const float* oW2    = (const float*)d_in[19];
    const float* oB2    = (const float*)d_in[20];

    const int N = in_sizes[1] / 3;
    const int E = in_sizes[2] / 2;
    const int Etot = E + N;
    const int INDIM = in_sizes[0] / N;

    float *bh, *bA, *bB, *bagg, *bT, *bpos, *bdpos, *bwn;
    unsigned* bwp;
    cudaGetSymbolAddress((void**)&bh, g_h);
    cudaGetSymbolAddress((void**)&bA, g_A);
    cudaGetSymbolAddress((void**)&bB, g_B);
    cudaGetSymbolAddress((void**)&bagg, g_agg);
    cudaGetSymbolAddress((void**)&bT, g_T);
    cudaGetSymbolAddress((void**)&bpos, g_pos);
    cudaGetSymbolAddress((void**)&bdpos, g_dpos);
    cudaGetSymbolAddress((void**)&bwn, g_wnode);
    cudaGetSymbolAddress((void**)&bwp, g_wpack);

    // ---- pack-job table: emb, {cW1,W1a,W1b,nW1,nW2,msgW2}x4, oW1, oW2 -------
    PackJobs jobs;
    unsigned embOff, cW1Off[LAYERS], W1aOff[LAYERS], W1bOff[LAYERS];
    unsigned nW1Off[LAYERS], nW2Off[LAYERS], mW2Off[LAYERS], oW1Off, oW2Off;
    {
        int j = 0; unsigned off = 0; int boff = 0;
        auto add = [&](const float* src, int nkk, unsigned* offOut) {
            jobs.src[j] = src; jobs.dstOff[j] = off; jobs.blockOff[j] = boff;
            *offOut = off; off += (unsigned)nkk * 256; boff += nkk; ++j;
        };
        add(embW, INDIM / 8, &embOff);
        for (int l = 0; l < LAYERS; ++l) {
            add(cW1 + (size_t)l * H * H, 16, &cW1Off[l]);
            add(msgW1 + (size_t)l * 257 * H, 16, &W1aOff[l]);
            add(msgW1 + (size_t)l * 257 * H + 128 * H, 16, &W1bOff[l]);
            add(nW1 + (size_t)l * 2 * H * H, 32, &nW1Off[l]);
            add(nW2 + (size_t)l * H * H, 16, &nW2Off[l]);
            add(msgW2 + (size_t)l * H * H, 16, &mW2Off[l]);
        }
        add(oW1, 16, &oW1Off);
        add(oW2, 16, &oW2Off);
        jobs.njobs = j;
        jobs.blockOff[j] = boff;
        packw_kernel<<<boff, 256>>>(jobs, bwp);
    }
    const uint4* wp4 = (const uint4*)bwp;

    const int NODE_SMEM = 64 * FR * 4;                 // 33792 B
    const int EDGE_SMEM = 64 * FR * 4 + 3 * TE * 4;
    cudaFuncSetAttribute(node_gemm,
                         cudaFuncAttributeMaxDynamicSharedMemorySize, NODE_SMEM);
    cudaFuncSetAttribute(fused3_gemm,
                         cudaFuncAttributeMaxDynamicSharedMemorySize, NODE_SMEM);
    cudaFuncSetAttribute(edge_kernel,
                         cudaFuncAttributeMaxDynamicSharedMemorySize, EDGE_SMEM);

    const int gn = (N + 63) / 64;
    const int tinit = (N * H + 255) / 256;
    const int t256p = (N * 3 + 255) / 256;

    // embedding + pos/dpos/agg init
    node_gemm<<<gn, 256, NODE_SMEM>>>(h_in, INDIM, nullptr, 0, wp4 + embOff,
                                      embB, nullptr, 0, bh, N, nullptr);
    init_kernel<<<tinit, 256>>>(bpos, pos_in, bdpos, N * 3, bagg, N * H);

    for (int l = 0; l < LAYERS; ++l) {
        const float* W1c = msgW1 + (size_t)l * 257 * H + 256 * H;

        fused3_gemm<<<dim3(gn, 3), 256, NODE_SMEM>>>(
            bh, wp4 + cW1Off[l], cB1 + l * H, cW2 + (size_t)l * H, cB2 + l, bwn,
            wp4 + W1aOff[l], wp4 + W1bOff[l], bA, bB, N);

        edge_kernel<<<444, 256, EDGE_SMEM>>>(
            ei, E, Etot, bA, bB, bpos, bwn,
            (const unsigned*)(wp4 + mW2Off[l]), msgB1 + l * H, msgB2 + l * H, W1c,
            bagg, bdpos);

        node_gemm<<<gn, 256, NODE_SMEM>>>(bh, H, bagg, H, wp4 + nW1Off[l],
                                          nB1 + l * H, nullptr, 1, bT, N, bagg);
        node_gemm<<<gn, 256, NODE_SMEM>>>(bT, H, nullptr, 0, wp4 + nW2Off[l],
                                          nB2 + l * H, bh, 0, bh, N, nullptr);
        addzero_kernel<<<t256p, 256>>>(bpos, bdpos, N * 3);
    }

    node_gemm<<<gn, 256, NODE_SMEM>>>(bh, H, nullptr, 0, wp4 + oW1Off, oB1,
                                      nullptr, 1, bT, N, nullptr);
    node_gemm<<<gn, 256, NODE_SMEM>>>(bT, H, nullptr, 0, wp4 + oW2Off, oB2,
                                      nullptr, 0, (float*)d_out, N, nullptr);

    if (out_size >= N * H + N * 3) {
        copy_kernel<<<t256p, 256>>>((float*)d_out + (size_t)N * H, bpos, N * 3);
    }
}